// round 16
// baseline (speedup 1.0000x reference)
#include <cuda_runtime.h>
#include <cuda_fp16.h>
#include <cstdint>

#define BATCH 1024
#define NSTEPS 25

// scratch (device globals)
__device__ __half g_xh[BATCH * 8192];             // pooled spikes after conv2 (fp16, exact)
__device__ __half g_wh0[256 * 8192];              // fc1_w hi split
__device__ __half g_wh1[256 * 8192];              // fc1_w lo split
__device__ float  g_part[4 * 1024 * 256];         // fc1 K-split partials

// ---------------------------------------------------------------------------
// mma.sync m16n8k16 fp16 (baseline PTX)
// ---------------------------------------------------------------------------
__device__ __forceinline__ void mma_f16(float* d, const uint32_t* a, const uint32_t* b) {
    asm volatile(
        "mma.sync.aligned.m16n8k16.row.col.f32.f16.f16.f32 "
        "{%0,%1,%2,%3}, {%4,%5,%6,%7}, {%8,%9}, {%0,%1,%2,%3};"
        : "+f"(d[0]), "+f"(d[1]), "+f"(d[2]), "+f"(d[3])
        : "r"(a[0]), "r"(a[1]), "r"(a[2]), "r"(a[3]), "r"(b[0]), "r"(b[1]));
}
__device__ __forceinline__ uint32_t packh(__half a, __half b) {
    return (uint32_t)__half_as_ushort(a) | ((uint32_t)__half_as_ushort(b) << 16);
}

// ---------------------------------------------------------------------------
// Kernel A: split fc1_w into 2 fp16 planes (once)
// ---------------------------------------------------------------------------
__global__ void __launch_bounds__(256) wprep_kernel(const float* __restrict__ W) {
    int i = blockIdx.x * 256 + threadIdx.x;
    if (i < 256 * 8192) {
        float w = W[i];
        __half h0 = __float2half(w);
        g_wh0[i] = h0;
        g_wh1[i] = __float2half(w - __half2float(h0));
    }
}

// ---------------------------------------------------------------------------
// Kernel B: FUSED conv1 + conv2, SOFTWARE-PIPELINED:
//   double-buffered sIn; conv1(img n+1) overlaps (cross-warp) with mma(img n).
//   2 syncs/image. Identical math/order to R13 (rel_err 0 lineage).
// ---------------------------------------------------------------------------
#define C2_BUF_HALves 29376                           // 34*18*48
#define C2_AF_OFF   0
#define C2_AF_BYTES 73728                             // 2*4*18*128 u32
#define C2_IN_OFF   73728                             // 2 buffers x 58752 B
#define C2_X1_OFF   (C2_IN_OFF + 2 * 58752)           // 191232
#define C2_W1_OFF   (C2_X1_OFF + 66 * 34 * 4)         // 200208
#define C2_SMEM     (C2_W1_OFF + 320 * 4)             // 201488

__global__ void __launch_bounds__(512, 1) conv12_mma(const float* __restrict__ x,
                                                     const float* __restrict__ w1,
                                                     const float* __restrict__ b1,
                                                     const float* __restrict__ w2,
                                                     const float* __restrict__ b2) {
    extern __shared__ char sm[];
    uint32_t* sAf = (uint32_t*)(sm + C2_AF_OFF);
    __half* sIn = (__half*)(sm + C2_IN_OFF);          // [2][34][18][48]
    float* sX1 = (float*)(sm + C2_X1_OFF);
    float* sW1 = (float*)(sm + C2_W1_OFF);            // 288 w + 32 bias

    const int t = threadIdx.x;
    const int lane = t & 31, wid = t >> 5;
    const int wm = wid & 1, wn = wid >> 1;

    // zero both buffers (halos persist); stage conv1 weights
    for (int i = t; i < 2 * 58752 / 4; i += 512) ((uint32_t*)sIn)[i] = 0u;
    for (int i = t; i < 66 * 34; i += 512) sX1[i] = 0.f;
    for (int i = t; i < 288; i += 512) sW1[i] = w1[i];
    if (t < 32) sW1[288 + t] = b1[t];

    // conv2 weight fragments, 2 fp16 splits, K order (tap, ci)
    for (int idx = t; idx < 4 * 18 * 32 * 4; idx += 512) {
        int r = idx & 3, ln = (idx >> 2) & 31, ks = (idx >> 7) % 18, mt = idx / (128 * 18);
        int oc = mt * 16 + (ln >> 2) + (r & 1) * 8;
        int kk = (ln & 3) * 2 + (r >> 1) * 8;
        int tap = ks >> 1, ci0 = (ks & 1) * 16;
        float w0 = w2[oc * 288 + (ci0 + kk) * 9 + tap];
        float w1v = w2[oc * 288 + (ci0 + kk + 1) * 9 + tap];
#pragma unroll
        for (int s = 0; s < 2; s++) {
            __half h0 = __float2half(w0);
            __half h1 = __float2half(w1v);
            w0 -= __half2float(h0);
            w1v -= __half2float(h1);
            sAf[((s * 4 + mt) * 18 + ks) * 128 + ln * 4 + r] = packh(h0, h1);
        }
    }

    float biasr[2][2];
#pragma unroll
    for (int ml = 0; ml < 2; ml++) {
        int mt = wm * 2 + ml;
        biasr[ml][0] = b2[mt * 16 + (lane >> 2)];
        biasr[ml][1] = b2[mt * 16 + (lane >> 2) + 8];
    }

    int posoff[8];
#pragma unroll
    for (int nt = 0; nt < 8; nt++) {
        int pos = wn * 64 + nt * 8 + (lane >> 2);
        posoff[nt] = ((pos >> 4) * 18 + (pos & 15)) * 48;
    }

    const int ph1 = t >> 4, pw1 = t & 15;
    const int sInCellBase = ((ph1 + 1) * 18 + (pw1 + 1)) * 48;
    __syncthreads();

    // ---- prologue: stage + conv1 for this CTA's first image into buf 0 ----
    {
        const float* xi = x + blockIdx.x * 2048;
        float4 v = ((const float4*)xi)[t];
        int y = t >> 3, xc = (t & 7) * 4;
        float* p = sX1 + (y + 1) * 34 + xc + 1;
        p[0] = v.x; p[1] = v.y; p[2] = v.z; p[3] = v.w;
    }
    __syncthreads();
    {
        float in[4][4];
#pragma unroll
        for (int r = 0; r < 4; r++)
#pragma unroll
            for (int c = 0; c < 4; c++)
                in[r][c] = sX1[(2 * ph1 + r) * 34 + (2 * pw1 + c)];
        __half* dst = sIn + sInCellBase;
#pragma unroll 4
        for (int ch = 0; ch < 32; ch++) {
            float wv[9];
#pragma unroll
            for (int k = 0; k < 9; k++) wv[k] = sW1[ch * 9 + k];
            float bb = sW1[288 + ch];
            float cnt = 0.f;
#pragma unroll
            for (int dy = 0; dy < 2; dy++)
#pragma unroll
                for (int dx = 0; dx < 2; dx++) {
                    float s = bb;
#pragma unroll
                    for (int ky = 0; ky < 3; ky++)
#pragma unroll
                        for (int kx = 0; kx < 3; kx++)
                            s += wv[ky * 3 + kx] * in[dy + ky][dx + kx];
                    cnt += (s > 1.f) ? 1.f : 0.f;
                }
            int np = (ch & 16) + ((ch & 6) << 1) + (ch & 1) + (((ch >> 3) & 1) << 1);
            dst[np] = __float2half(cnt * 0.25f);
        }
    }

    for (int k = 0;; k++) {
        const int img = blockIdx.x + k * 148;
        if (img >= BATCH) break;
        const int next = img + 148;
        const bool hasNext = (next < BATCH);

        __syncthreads();   // conv1(buf k&1) visible; prev mma done with buf we'll write

        // stage next raw input
        if (hasNext) {
            const float* xi = x + next * 2048;
            float4 v = ((const float4*)xi)[t];
            int y = t >> 3, xc = (t & 7) * 4;
            float* p = sX1 + (y + 1) * 34 + xc + 1;
            p[0] = v.x; p[1] = v.y; p[2] = v.z; p[3] = v.w;
        }
        __syncthreads();   // sX1 visible

        // conv1(next) -> other buffer (overlaps cross-warp with mma below)
        if (hasNext) {
            float in[4][4];
#pragma unroll
            for (int r = 0; r < 4; r++)
#pragma unroll
                for (int c = 0; c < 4; c++)
                    in[r][c] = sX1[(2 * ph1 + r) * 34 + (2 * pw1 + c)];
            __half* dst = sIn + ((k + 1) & 1) * C2_BUF_HALves + sInCellBase;
#pragma unroll 4
            for (int ch = 0; ch < 32; ch++) {
                float wv[9];
#pragma unroll
                for (int kk2 = 0; kk2 < 9; kk2++) wv[kk2] = sW1[ch * 9 + kk2];
                float bb = sW1[288 + ch];
                float cnt = 0.f;
#pragma unroll
                for (int dy = 0; dy < 2; dy++)
#pragma unroll
                    for (int dx = 0; dx < 2; dx++) {
                        float s = bb;
#pragma unroll
                        for (int ky = 0; ky < 3; ky++)
#pragma unroll
                            for (int kx = 0; kx < 3; kx++)
                                s += wv[ky * 3 + kx] * in[dy + ky][dx + kx];
                        cnt += (s > 1.f) ? 1.f : 0.f;
                    }
                int np = (ch & 16) + ((ch & 6) << 1) + (ch & 1) + (((ch >> 3) & 1) << 1);
                dst[np] = __float2half(cnt * 0.25f);
            }
        }

        // conv2 mainloop for current image (reads buf k&1)
        const __half* sInb = sIn + (k & 1) * C2_BUF_HALves;
        float acc[2][8][4];
#pragma unroll
        for (int ml = 0; ml < 2; ml++)
#pragma unroll
            for (int nt = 0; nt < 8; nt++)
#pragma unroll
                for (int q = 0; q < 4; q++) acc[ml][nt][q] = 0.f;

#pragma unroll 2
        for (int ks = 0; ks < 18; ks++) {
            int tap = ks >> 1, ci0 = (ks & 1) * 16;
            int dy = tap / 3, dx = tap - dy * 3;
            int toff = (dy * 18 + dx) * 48 + ci0 + (lane & 3) * 4;

            uint32_t bfr[8][2];
#pragma unroll
            for (int nt = 0; nt < 8; nt++) {
                uint2 bv = *(const uint2*)(sInb + posoff[nt] + toff);
                bfr[nt][0] = bv.x; bfr[nt][1] = bv.y;
            }
#pragma unroll
            for (int s = 0; s < 2; s++)
#pragma unroll
                for (int ml = 0; ml < 2; ml++) {
                    int mt = wm * 2 + ml;
                    uint4 av = ((const uint4*)(sAf + ((s * 4 + mt) * 18 + ks) * 128))[lane];
                    uint32_t a[4] = {av.x, av.y, av.z, av.w};
#pragma unroll
                    for (int nt = 0; nt < 8; nt++)
                        mma_f16(acc[ml][nt], a, bfr[nt]);
                }
        }

        // epilogue: +bias, spike, in-thread 2x2 pool
        __half* xout = g_xh + img * 8192;
#pragma unroll
        for (int ml = 0; ml < 2; ml++)
#pragma unroll
            for (int rh = 0; rh < 2; rh++) {
                int ch = (wm * 2 + ml) * 16 + (lane >> 2) + rh * 8;
                float bv = biasr[ml][rh];
#pragma unroll
                for (int np2 = 0; np2 < 4; np2++) {
                    int nt = (np2 & 1) + (np2 >> 1) * 4;   // {0,1,4,5}
                    float s0 = (acc[ml][nt][rh * 2]         + bv > 1.f) ? 1.f : 0.f;
                    float s1 = (acc[ml][nt][rh * 2 + 1]     + bv > 1.f) ? 1.f : 0.f;
                    float s2 = (acc[ml][nt + 2][rh * 2]     + bv > 1.f) ? 1.f : 0.f;
                    float s3 = (acc[ml][nt + 2][rh * 2 + 1] + bv > 1.f) ? 1.f : 0.f;
                    int h = wn * 4 + (nt >> 1);
                    int ph = h >> 1;
                    int pw = (nt & 1) * 4 + (lane & 3);
                    xout[ch * 128 + ph * 8 + pw] = __float2half((s0 + s1 + s2 + s3) * 0.25f);
                }
            }
    }
}

// ---------------------------------------------------------------------------
// Kernel 3: fc1 via mma.sync fp16 (pre-split planes), split-K=4, dbl-buffer.
// ---------------------------------------------------------------------------
#define FC1_SMEM ((2 * 2304 + 4 * 2304) * 4)   // 55296 B

__global__ void __launch_bounds__(256) fc1_mma() {
    extern __shared__ uint32_t smf[];
    uint32_t* sX = smf;
    uint32_t* sW2 = smf + 2 * 2304;

    const int t = threadIdx.x;
    const int lane = t & 31, wid = t >> 5;
    const int wm = wid & 1, wn = wid >> 1;
    const int rowbase = blockIdx.x * 64;
    const int n0 = blockIdx.y * 64;
    const int k0 = blockIdx.z * 2048;

    const int lrow = t >> 2, lk16 = (t & 3) * 16, lk8 = (t & 3) * 8;

    const uint4* xsrc  = (const uint4*)(g_xh  + (rowbase + lrow) * 8192 + k0 + lk16);
    const uint4* w0src = (const uint4*)(g_wh0 + (n0 + lrow) * 8192 + k0 + lk16);
    const uint4* w1src = (const uint4*)(g_wh1 + (n0 + lrow) * 8192 + k0 + lk16);

    float acc[2][2][4];
#pragma unroll
    for (int mt = 0; mt < 2; mt++)
#pragma unroll
        for (int nt = 0; nt < 2; nt++)
#pragma unroll
            for (int q = 0; q < 4; q++) acc[mt][nt][q] = 0.f;

    uint4 xr0, xr1, wa0, wa1, wb0, wb1;
    xr0 = xsrc[0];  xr1 = xsrc[1];
    wa0 = w0src[0]; wa1 = w0src[1];
    wb0 = w1src[0]; wb1 = w1src[1];

    {
        uint32_t* xd = sX + lrow * 36 + lk8;
        xd[0] = xr0.x; xd[1] = xr0.y; xd[2] = xr0.z; xd[3] = xr0.w;
        xd[4] = xr1.x; xd[5] = xr1.y; xd[6] = xr1.z; xd[7] = xr1.w;
        uint32_t* w0d = sW2 + lrow * 36 + lk8;
        w0d[0] = wa0.x; w0d[1] = wa0.y; w0d[2] = wa0.z; w0d[3] = wa0.w;
        w0d[4] = wa1.x; w0d[5] = wa1.y; w0d[6] = wa1.z; w0d[7] = wa1.w;
        uint32_t* w1d = sW2 + 2304 + lrow * 36 + lk8;
        w1d[0] = wb0.x; w1d[1] = wb0.y; w1d[2] = wb0.z; w1d[3] = wb0.w;
        w1d[4] = wb1.x; w1d[5] = wb1.y; w1d[6] = wb1.z; w1d[7] = wb1.w;
    }

    for (int kc = 0; kc < 32; kc++) {
        const int cb = kc & 1;
        if (kc < 31) {
            xr0 = xsrc[(kc + 1) * 8];  xr1 = xsrc[(kc + 1) * 8 + 1];
            wa0 = w0src[(kc + 1) * 8]; wa1 = w0src[(kc + 1) * 8 + 1];
            wb0 = w1src[(kc + 1) * 8]; wb1 = w1src[(kc + 1) * 8 + 1];
        }
        __syncthreads();

        const uint32_t* xb = sX + cb * 2304;
        const uint32_t* wb = sW2 + cb * 2 * 2304;
#pragma unroll
        for (int ks = 0; ks < 4; ks++) {
            const int kw = ks * 8 + (lane & 3);
            uint32_t a[2][4];
#pragma unroll
            for (int mt = 0; mt < 2; mt++) {
                int row = wm * 32 + mt * 16 + (lane >> 2);
                a[mt][0] = xb[row * 36 + kw];
                a[mt][1] = xb[(row + 8) * 36 + kw];
                a[mt][2] = xb[row * 36 + kw + 4];
                a[mt][3] = xb[(row + 8) * 36 + kw + 4];
            }
#pragma unroll
            for (int s = 0; s < 2; s++)
#pragma unroll
                for (int nt = 0; nt < 2; nt++) {
                    int n = wn * 16 + nt * 8 + (lane >> 2);
                    uint32_t b[2];
                    b[0] = wb[s * 2304 + n * 36 + kw];
                    b[1] = wb[s * 2304 + n * 36 + kw + 4];
#pragma unroll
                    for (int mt = 0; mt < 2; mt++)
                        mma_f16(acc[mt][nt], a[mt], b);
                }
        }

        if (kc < 31) {
            const int nb = cb ^ 1;
            uint32_t* xd = sX + nb * 2304 + lrow * 36 + lk8;
            xd[0] = xr0.x; xd[1] = xr0.y; xd[2] = xr0.z; xd[3] = xr0.w;
            xd[4] = xr1.x; xd[5] = xr1.y; xd[6] = xr1.z; xd[7] = xr1.w;
            uint32_t* w0d = sW2 + nb * 2 * 2304 + lrow * 36 + lk8;
            w0d[0] = wa0.x; w0d[1] = wa0.y; w0d[2] = wa0.z; w0d[3] = wa0.w;
            w0d[4] = wa1.x; w0d[5] = wa1.y; w0d[6] = wa1.z; w0d[7] = wa1.w;
            uint32_t* w1d = w0d + 2304;
            w1d[0] = wb0.x; w1d[1] = wb0.y; w1d[2] = wb0.z; w1d[3] = wb0.w;
            w1d[4] = wb1.x; w1d[5] = wb1.y; w1d[6] = wb1.z; w1d[7] = wb1.w;
        }
    }

    float* outp = g_part + blockIdx.z * (1024 * 256);
    const int r0 = rowbase + wm * 32 + (lane >> 2);
    const int c0 = n0 + wn * 16 + (lane & 3) * 2;
#pragma unroll
    for (int mt = 0; mt < 2; mt++)
#pragma unroll
        for (int nt = 0; nt < 2; nt++) {
            int r = r0 + mt * 16, c = c0 + nt * 8;
            outp[r * 256 + c]           = acc[mt][nt][0];
            outp[r * 256 + c + 1]       = acc[mt][nt][1];
            outp[(r + 8) * 256 + c]     = acc[mt][nt][2];
            outp[(r + 8) * 256 + c + 1] = acc[mt][nt][3];
        }
}

// ---------------------------------------------------------------------------
// Kernel 4: 25-step LIF recurrence — R13 version (reg-resident fc2 frags)
// ---------------------------------------------------------------------------
#define REC_SMEM_BYTES ((32768 + 1280 + 128 + 16 + 256 + 1056 + 1024 + 160) * 4)

__global__ void __launch_bounds__(512, 1) rec_kernel(const float* __restrict__ w2,
                                                     const float* __restrict__ b2,
                                                     const float* __restrict__ w3,
                                                     const float* __restrict__ b3,
                                                     const float* __restrict__ b1,
                                                     float* __restrict__ out) {
    extern __shared__ uint32_t smu[];
    uint32_t* w4f   = smu;
    float* w3s      = (float*)(smu + 32768);
    float* b2s      = w3s + 1280;
    float* b3s      = b2s + 128;
    float* b1s      = b3s + 16;
    __half* spk3h   = (__half*)(b1s + 256);
    float* spk4s    = (float*)((uint32_t*)(b1s + 256) + 1056);
    float* part5    = spk4s + 1024;

    const int t = threadIdx.x;
    const int lane = t & 31, wid = t >> 5;
    const int rowbase = blockIdx.x * 8;

    for (int idx = t; idx < 32768; idx += 512) {
        int reg = idx & 1, ln = (idx >> 1) & 31, s = (idx >> 6) & 1;
        int ks = (idx >> 7) & 15, w = idx >> 11;
        int n = w * 8 + (ln >> 2);
        int kb = ks * 16 + (ln & 3) * 2 + reg * 8;
        float w0 = w2[n * 256 + kb], w1v = w2[n * 256 + kb + 1];
        __half h0, h1;
        if (s == 0) { h0 = __float2half(w0); h1 = __float2half(w1v); }
        else {
            h0 = __float2half(w0 - __half2float(__float2half(w0)));
            h1 = __float2half(w1v - __half2float(__float2half(w1v)));
        }
        w4f[idx] = packh(h0, h1);
    }
    for (int idx = t; idx < 1280; idx += 512) {
        int j = idx >> 7, k = idx & 127;
        w3s[k * 10 + j] = w3[idx];
    }
    if (t < 128) b2s[t] = b2[t];
    if (t < 10)  b3s[t] = b3[t];
    if (t < 256) b1s[t] = b1[t];
    __syncthreads();

    uint2 wreg[16][2];
    {
        const uint32_t* wb = w4f + wid * 2048;
#pragma unroll
        for (int ks = 0; ks < 16; ks++) {
            wreg[ks][0] = *(const uint2*)(wb + ks * 128 + lane * 2);
            wreg[ks][1] = *(const uint2*)(wb + ks * 128 + 64 + lane * 2);
        }
    }

    const int n3 = t & 255, rh = t >> 8;
    float mem3[4], c3[4];
    const int QS = 1024 * 256;
#pragma unroll
    for (int r = 0; r < 4; r++) {
        int row = rowbase + rh * 4 + r;
        mem3[r] = 0.f;
        int off = row * 256 + n3;
        c3[r] = ((g_part[off] + g_part[off + QS]) +
                 (g_part[off + 2 * QS] + g_part[off + 3 * QS])) + b1s[n3];
    }

    const int g4 = lane >> 2, q4 = lane & 3;
    float mem40 = 0.f, mem41 = 0.f;
    const float b2v0 = b2s[wid * 8 + q4 * 2];
    const float b2v1 = b2s[wid * 8 + q4 * 2 + 1];
    float mem5 = 0.f;
    const int rj5 = t % 80, kh5 = (t < 80) ? 0 : 1;
    const int r5 = rj5 / 10, j5 = rj5 % 10;
    const float b3v = (t < 80) ? b3s[j5] : 0.f;

    for (int step = 0; step < NSTEPS; step++) {
#pragma unroll
        for (int r = 0; r < 4; r++) {
            float reset = (mem3[r] > 1.f) ? 1.f : 0.f;
            float m = 0.95f * mem3[r] + c3[r] - reset;
            mem3[r] = m;
            spk3h[(rh * 4 + r) * 264 + n3] = __float2half((m > 1.f) ? 1.f : 0.f);
        }
        __syncthreads();

        {
            float c0[4] = {0.f, 0.f, 0.f, 0.f};
            float c1[4] = {0.f, 0.f, 0.f, 0.f};
            uint32_t a[4];
            a[1] = 0u; a[3] = 0u;
            const __half* ab = spk3h + g4 * 264 + q4 * 2;
#pragma unroll
            for (int ks = 0; ks < 16; ks++) {
                a[0] = *(const uint32_t*)(ab + ks * 16);
                a[2] = *(const uint32_t*)(ab + ks * 16 + 8);
                mma_f16(c0, a, (const uint32_t*)&wreg[ks][0]);
                mma_f16(c1, a, (const uint32_t*)&wreg[ks][1]);
            }
            float cur0 = (c0[0] + c1[0]) + b2v0;
            float cur1 = (c0[1] + c1[1]) + b2v1;
            float reset0 = (mem40 > 1.f) ? 1.f : 0.f;
            float m0 = 0.95f * mem40 + cur0 - reset0;
            mem40 = m0;
            float reset1 = (mem41 > 1.f) ? 1.f : 0.f;
            float m1 = 0.95f * mem41 + cur1 - reset1;
            mem41 = m1;
            int j0 = wid * 8 + q4 * 2;
            spk4s[j0 * 8 + g4]       = (m0 > 1.f) ? 1.f : 0.f;
            spk4s[(j0 + 1) * 8 + g4] = (m1 > 1.f) ? 1.f : 0.f;
        }
        __syncthreads();

        if (t < 160) {
            float a5 = 0.f;
            const int k0 = kh5 * 64;
#pragma unroll 8
            for (int k = k0; k < k0 + 64; k++)
                a5 += w3s[k * 10 + j5] * spk4s[k * 8 + r5];
            part5[kh5 * 80 + rj5] = a5;
        }
        __syncthreads();

        if (t < 80) {
            float a5 = b3v + (part5[t] + part5[80 + t]);
            float reset = (mem5 > 1.f) ? 1.f : 0.f;
            float m = 0.95f * mem5 + a5 - reset;
            mem5 = m;
            out[(step * 1024 + rowbase + r5) * 10 + j5] = (m > 1.f) ? 1.f : 0.f;
        }
    }
}

// ---------------------------------------------------------------------------
extern "C" void kernel_launch(void* const* d_in, const int* in_sizes, int n_in,
                              void* d_out, int out_size) {
    const float* x       = (const float*)d_in[0];
    const float* conv1_w = (const float*)d_in[1];
    const float* conv1_b = (const float*)d_in[2];
    const float* conv2_w = (const float*)d_in[3];
    const float* conv2_b = (const float*)d_in[4];
    const float* fc1_w   = (const float*)d_in[5];
    const float* fc1_b   = (const float*)d_in[6];
    const float* fc2_w   = (const float*)d_in[7];
    const float* fc2_b   = (const float*)d_in[8];
    const float* fc3_w   = (const float*)d_in[9];
    const float* fc3_b   = (const float*)d_in[10];
    float* out = (float*)d_out;

    cudaFuncSetAttribute(conv12_mma, cudaFuncAttributeMaxDynamicSharedMemorySize,
                         C2_SMEM);
    cudaFuncSetAttribute(fc1_mma, cudaFuncAttributeMaxDynamicSharedMemorySize,
                         FC1_SMEM);
    cudaFuncSetAttribute(rec_kernel, cudaFuncAttributeMaxDynamicSharedMemorySize,
                         REC_SMEM_BYTES);

    wprep_kernel<<<8192, 256>>>(fc1_w);
    conv12_mma<<<148, 512, C2_SMEM>>>(x, conv1_w, conv1_b, conv2_w, conv2_b);
    fc1_mma<<<dim3(16, 4, 4), 256, FC1_SMEM>>>();
    rec_kernel<<<128, 512, REC_SMEM_BYTES>>>(fc2_w, fc2_b, fc3_w, fc3_b, fc1_b, out);
}

// round 17
// speedup vs baseline: 1.0271x; 1.0271x over previous
#include <cuda_runtime.h>
#include <cuda_fp16.h>
#include <cstdint>

#define BATCH 1024
#define NSTEPS 25

// scratch (device globals)
__device__ __half g_xh[BATCH * 8192];             // pooled spikes after conv2 (fp16, exact)
__device__ __half g_wh0[256 * 8192];              // fc1_w hi split
__device__ __half g_wh1[256 * 8192];              // fc1_w lo split
__device__ float  g_part[4 * 1024 * 256];         // fc1 K-split partials

// ---------------------------------------------------------------------------
// mma.sync m16n8k16 fp16 (baseline PTX)
// ---------------------------------------------------------------------------
__device__ __forceinline__ void mma_f16(float* d, const uint32_t* a, const uint32_t* b) {
    asm volatile(
        "mma.sync.aligned.m16n8k16.row.col.f32.f16.f16.f32 "
        "{%0,%1,%2,%3}, {%4,%5,%6,%7}, {%8,%9}, {%0,%1,%2,%3};"
        : "+f"(d[0]), "+f"(d[1]), "+f"(d[2]), "+f"(d[3])
        : "r"(a[0]), "r"(a[1]), "r"(a[2]), "r"(a[3]), "r"(b[0]), "r"(b[1]));
}
__device__ __forceinline__ uint32_t packh(__half a, __half b) {
    return (uint32_t)__half_as_ushort(a) | ((uint32_t)__half_as_ushort(b) << 16);
}

// ---------------------------------------------------------------------------
// Kernel A: split fc1_w into 2 fp16 planes (once)
// ---------------------------------------------------------------------------
__global__ void __launch_bounds__(256) wprep_kernel(const float* __restrict__ W) {
    int i = blockIdx.x * 256 + threadIdx.x;
    if (i < 256 * 8192) {
        float w = W[i];
        __half h0 = __float2half(w);
        g_wh0[i] = h0;
        g_wh1[i] = __float2half(w - __half2float(h0));
    }
}

// ---------------------------------------------------------------------------
// Kernel B: FUSED conv1 + conv2, WARP-SPECIALIZED pipeline:
//   warps 8-15 (producers): stage x(next) + conv1(next) -> buf[(k+1)&1]
//   warps 0-7  (consumers): conv2 mma + epilogue for img k from buf[k&1]
//   fma pipe (conv1) and tensor pipe (mma) run concurrently per SMSP.
// ---------------------------------------------------------------------------
#define C2_BUF_H    29376                             // 34*18*48 halves
#define C2_AF_OFF   0
#define C2_AF_BYTES 73728                             // 2*4*18*128 u32
#define C2_IN_OFF   73728                             // 2 buffers x 58752 B
#define C2_X1_OFF   (C2_IN_OFF + 2 * 58752)           // 191232
#define C2_W1_OFF   (C2_X1_OFF + 66 * 34 * 4)         // 200208
#define C2_SMEM     (C2_W1_OFF + 320 * 4)             // 201488

__global__ void __launch_bounds__(512, 1) conv12_mma(const float* __restrict__ x,
                                                     const float* __restrict__ w1,
                                                     const float* __restrict__ b1,
                                                     const float* __restrict__ w2,
                                                     const float* __restrict__ b2) {
    extern __shared__ char sm[];
    uint32_t* sAf = (uint32_t*)(sm + C2_AF_OFF);
    __half* sIn = (__half*)(sm + C2_IN_OFF);          // [2][34][18][48]
    float* sX1 = (float*)(sm + C2_X1_OFF);
    float* sW1 = (float*)(sm + C2_W1_OFF);            // 288 w + 32 bias

    const int t = threadIdx.x;
    const int lane = t & 31, wid = t >> 5;

    // zero both buffers (halos persist); stage conv1 weights
    for (int i = t; i < 2 * 58752 / 4; i += 512) ((uint32_t*)sIn)[i] = 0u;
    for (int i = t; i < 66 * 34; i += 512) sX1[i] = 0.f;
    for (int i = t; i < 288; i += 512) sW1[i] = w1[i];
    if (t < 32) sW1[288 + t] = b1[t];

    // conv2 weight fragments, 2 fp16 splits, K order (tap, ci)
    for (int idx = t; idx < 4 * 18 * 32 * 4; idx += 512) {
        int r = idx & 3, ln = (idx >> 2) & 31, ks = (idx >> 7) % 18, mt = idx / (128 * 18);
        int oc = mt * 16 + (ln >> 2) + (r & 1) * 8;
        int kk = (ln & 3) * 2 + (r >> 1) * 8;
        int tap = ks >> 1, ci0 = (ks & 1) * 16;
        float w0 = w2[oc * 288 + (ci0 + kk) * 9 + tap];
        float w1v = w2[oc * 288 + (ci0 + kk + 1) * 9 + tap];
#pragma unroll
        for (int s = 0; s < 2; s++) {
            __half h0 = __float2half(w0);
            __half h1 = __float2half(w1v);
            w0 -= __half2float(h0);
            w1v -= __half2float(h1);
            sAf[((s * 4 + mt) * 18 + ks) * 128 + ln * 4 + r] = packh(h0, h1);
        }
    }

    // consumer role constants (warps 0-7): wm x wn, two 64-pos passes
    const int wm = wid & 1, wn = wid >> 1;            // wn 0..3 (consumers)
    float biasr[2][2];
#pragma unroll
    for (int ml = 0; ml < 2; ml++) {
        int mt = wm * 2 + ml;
        biasr[ml][0] = b2[mt * 16 + (lane >> 2)];
        biasr[ml][1] = b2[mt * 16 + (lane >> 2) + 8];
    }

    // producer role constants (warps 8-15)
    const int tp = t - 256;                           // 0..255 for producers
    const int php0 = (tp & 255) >> 4;                 // cells tp, tp+256
    const int pwp0 = tp & 15;

    // prologue conv1 cell (all 512 threads, one cell each)
    const int ph1 = t >> 4, pw1 = t & 15;
    __syncthreads();

    // ---- prologue: stage + conv1(first image) into buf 0 (all threads) ----
    {
        const float* xi = x + blockIdx.x * 2048;
        float4 v = ((const float4*)xi)[t];
        int y = t >> 3, xc = (t & 7) * 4;
        float* p = sX1 + (y + 1) * 34 + xc + 1;
        p[0] = v.x; p[1] = v.y; p[2] = v.z; p[3] = v.w;
    }
    __syncthreads();
    {
        float in[4][4];
#pragma unroll
        for (int r = 0; r < 4; r++)
#pragma unroll
            for (int c = 0; c < 4; c++)
                in[r][c] = sX1[(2 * ph1 + r) * 34 + (2 * pw1 + c)];
        __half* dst = sIn + ((ph1 + 1) * 18 + (pw1 + 1)) * 48;
#pragma unroll 4
        for (int ch = 0; ch < 32; ch++) {
            float wv[9];
#pragma unroll
            for (int k = 0; k < 9; k++) wv[k] = sW1[ch * 9 + k];
            float bb = sW1[288 + ch];
            float cnt = 0.f;
#pragma unroll
            for (int dy = 0; dy < 2; dy++)
#pragma unroll
                for (int dx = 0; dx < 2; dx++) {
                    float s = bb;
#pragma unroll
                    for (int ky = 0; ky < 3; ky++)
#pragma unroll
                        for (int kx = 0; kx < 3; kx++)
                            s += wv[ky * 3 + kx] * in[dy + ky][dx + kx];
                    cnt += (s > 1.f) ? 1.f : 0.f;
                }
            int np = (ch & 16) + ((ch & 6) << 1) + (ch & 1) + (((ch >> 3) & 1) << 1);
            dst[np] = __float2half(cnt * 0.25f);
        }
    }

    for (int k = 0;; k++) {
        const int img = blockIdx.x + k * 148;
        if (img >= BATCH) break;
        const int next = img + 148;
        const bool hasNext = (next < BATCH);

        __syncthreads();   // buf[k&1] ready; consumers done with buf[(k+1)&1]

        if (wid >= 8) {
            // ================= PRODUCERS: conv1(next) -> buf[(k+1)&1] ======
            if (hasNext) {
                const float* xi = x + next * 2048;
#pragma unroll
                for (int j = 0; j < 2; j++) {
                    int idx = tp + j * 256;
                    float4 v = ((const float4*)xi)[idx];
                    int y = idx >> 3, xc = (idx & 7) * 4;
                    float* p = sX1 + (y + 1) * 34 + xc + 1;
                    p[0] = v.x; p[1] = v.y; p[2] = v.z; p[3] = v.w;
                }
                asm volatile("bar.sync 1, 256;" ::: "memory");

                __half* bufn = sIn + ((k + 1) & 1) * C2_BUF_H;
#pragma unroll
                for (int cj = 0; cj < 2; cj++) {
                    int ph = php0 + cj * 16, pw = pwp0;
                    float in[4][4];
#pragma unroll
                    for (int r = 0; r < 4; r++)
#pragma unroll
                        for (int c = 0; c < 4; c++)
                            in[r][c] = sX1[(2 * ph + r) * 34 + (2 * pw + c)];
                    __half* dst = bufn + ((ph + 1) * 18 + (pw + 1)) * 48;
#pragma unroll 4
                    for (int ch = 0; ch < 32; ch++) {
                        float wv[9];
#pragma unroll
                        for (int kk2 = 0; kk2 < 9; kk2++) wv[kk2] = sW1[ch * 9 + kk2];
                        float bb = sW1[288 + ch];
                        float cnt = 0.f;
#pragma unroll
                        for (int dy = 0; dy < 2; dy++)
#pragma unroll
                            for (int dx = 0; dx < 2; dx++) {
                                float s = bb;
#pragma unroll
                                for (int ky = 0; ky < 3; ky++)
#pragma unroll
                                    for (int kx = 0; kx < 3; kx++)
                                        s += wv[ky * 3 + kx] * in[dy + ky][dx + kx];
                                cnt += (s > 1.f) ? 1.f : 0.f;
                            }
                        int np = (ch & 16) + ((ch & 6) << 1) + (ch & 1) + (((ch >> 3) & 1) << 1);
                        dst[np] = __float2half(cnt * 0.25f);
                    }
                }
            }
        } else {
            // ================= CONSUMERS: conv2 mma + epilogue (img) =======
            const __half* sInb = sIn + (k & 1) * C2_BUF_H;
            __half* xout = g_xh + img * 8192;

#pragma unroll
            for (int half = 0; half < 2; half++) {
                const int wnp = wn * 2 + half;   // 0..7: 64-position group
                int posoff[8];
#pragma unroll
                for (int nt = 0; nt < 8; nt++) {
                    int pos = wnp * 64 + nt * 8 + (lane >> 2);
                    posoff[nt] = ((pos >> 4) * 18 + (pos & 15)) * 48;
                }

                float acc[2][8][4];
#pragma unroll
                for (int ml = 0; ml < 2; ml++)
#pragma unroll
                    for (int nt = 0; nt < 8; nt++)
#pragma unroll
                        for (int q = 0; q < 4; q++) acc[ml][nt][q] = 0.f;

#pragma unroll 2
                for (int ks = 0; ks < 18; ks++) {
                    int tap = ks >> 1, ci0 = (ks & 1) * 16;
                    int dy = tap / 3, dx = tap - dy * 3;
                    int toff = (dy * 18 + dx) * 48 + ci0 + (lane & 3) * 4;

                    uint32_t bfr[8][2];
#pragma unroll
                    for (int nt = 0; nt < 8; nt++) {
                        uint2 bv = *(const uint2*)(sInb + posoff[nt] + toff);
                        bfr[nt][0] = bv.x; bfr[nt][1] = bv.y;
                    }
#pragma unroll
                    for (int s = 0; s < 2; s++)
#pragma unroll
                        for (int ml = 0; ml < 2; ml++) {
                            int mt = wm * 2 + ml;
                            uint4 av = ((const uint4*)(sAf + ((s * 4 + mt) * 18 + ks) * 128))[lane];
                            uint32_t a[4] = {av.x, av.y, av.z, av.w};
#pragma unroll
                            for (int nt = 0; nt < 8; nt++)
                                mma_f16(acc[ml][nt], a, bfr[nt]);
                        }
                }

#pragma unroll
                for (int ml = 0; ml < 2; ml++)
#pragma unroll
                    for (int rh = 0; rh < 2; rh++) {
                        int ch = (wm * 2 + ml) * 16 + (lane >> 2) + rh * 8;
                        float bv = biasr[ml][rh];
#pragma unroll
                        for (int np2 = 0; np2 < 4; np2++) {
                            int nt = (np2 & 1) + (np2 >> 1) * 4;   // {0,1,4,5}
                            float s0 = (acc[ml][nt][rh * 2]         + bv > 1.f) ? 1.f : 0.f;
                            float s1 = (acc[ml][nt][rh * 2 + 1]     + bv > 1.f) ? 1.f : 0.f;
                            float s2 = (acc[ml][nt + 2][rh * 2]     + bv > 1.f) ? 1.f : 0.f;
                            float s3 = (acc[ml][nt + 2][rh * 2 + 1] + bv > 1.f) ? 1.f : 0.f;
                            int h = wnp * 4 + (nt >> 1);
                            int ph = h >> 1;
                            int pw = (nt & 1) * 4 + (lane & 3);
                            xout[ch * 128 + ph * 8 + pw] = __float2half((s0 + s1 + s2 + s3) * 0.25f);
                        }
                    }
            }
        }
    }
}

// ---------------------------------------------------------------------------
// Kernel 3: fc1 via mma.sync fp16 (pre-split planes), split-K=4, dbl-buffer.
// ---------------------------------------------------------------------------
#define FC1_SMEM ((2 * 2304 + 4 * 2304) * 4)   // 55296 B

__global__ void __launch_bounds__(256) fc1_mma() {
    extern __shared__ uint32_t smf[];
    uint32_t* sX = smf;
    uint32_t* sW2 = smf + 2 * 2304;

    const int t = threadIdx.x;
    const int lane = t & 31, wid = t >> 5;
    const int wm = wid & 1, wn = wid >> 1;
    const int rowbase = blockIdx.x * 64;
    const int n0 = blockIdx.y * 64;
    const int k0 = blockIdx.z * 2048;

    const int lrow = t >> 2, lk16 = (t & 3) * 16, lk8 = (t & 3) * 8;

    const uint4* xsrc  = (const uint4*)(g_xh  + (rowbase + lrow) * 8192 + k0 + lk16);
    const uint4* w0src = (const uint4*)(g_wh0 + (n0 + lrow) * 8192 + k0 + lk16);
    const uint4* w1src = (const uint4*)(g_wh1 + (n0 + lrow) * 8192 + k0 + lk16);

    float acc[2][2][4];
#pragma unroll
    for (int mt = 0; mt < 2; mt++)
#pragma unroll
        for (int nt = 0; nt < 2; nt++)
#pragma unroll
            for (int q = 0; q < 4; q++) acc[mt][nt][q] = 0.f;

    uint4 xr0, xr1, wa0, wa1, wb0, wb1;
    xr0 = xsrc[0];  xr1 = xsrc[1];
    wa0 = w0src[0]; wa1 = w0src[1];
    wb0 = w1src[0]; wb1 = w1src[1];

    {
        uint32_t* xd = sX + lrow * 36 + lk8;
        xd[0] = xr0.x; xd[1] = xr0.y; xd[2] = xr0.z; xd[3] = xr0.w;
        xd[4] = xr1.x; xd[5] = xr1.y; xd[6] = xr1.z; xd[7] = xr1.w;
        uint32_t* w0d = sW2 + lrow * 36 + lk8;
        w0d[0] = wa0.x; w0d[1] = wa0.y; w0d[2] = wa0.z; w0d[3] = wa0.w;
        w0d[4] = wa1.x; w0d[5] = wa1.y; w0d[6] = wa1.z; w0d[7] = wa1.w;
        uint32_t* w1d = sW2 + 2304 + lrow * 36 + lk8;
        w1d[0] = wb0.x; w1d[1] = wb0.y; w1d[2] = wb0.z; w1d[3] = wb0.w;
        w1d[4] = wb1.x; w1d[5] = wb1.y; w1d[6] = wb1.z; w1d[7] = wb1.w;
    }

    for (int kc = 0; kc < 32; kc++) {
        const int cb = kc & 1;
        if (kc < 31) {
            xr0 = xsrc[(kc + 1) * 8];  xr1 = xsrc[(kc + 1) * 8 + 1];
            wa0 = w0src[(kc + 1) * 8]; wa1 = w0src[(kc + 1) * 8 + 1];
            wb0 = w1src[(kc + 1) * 8]; wb1 = w1src[(kc + 1) * 8 + 1];
        }
        __syncthreads();

        const uint32_t* xb = sX + cb * 2304;
        const uint32_t* wb = sW2 + cb * 2 * 2304;
#pragma unroll
        for (int ks = 0; ks < 4; ks++) {
            const int kw = ks * 8 + (lane & 3);
            uint32_t a[2][4];
#pragma unroll
            for (int mt = 0; mt < 2; mt++) {
                int row = wm * 32 + mt * 16 + (lane >> 2);
                a[mt][0] = xb[row * 36 + kw];
                a[mt][1] = xb[(row + 8) * 36 + kw];
                a[mt][2] = xb[row * 36 + kw + 4];
                a[mt][3] = xb[(row + 8) * 36 + kw + 4];
            }
#pragma unroll
            for (int s = 0; s < 2; s++)
#pragma unroll
                for (int nt = 0; nt < 2; nt++) {
                    int n = wn * 16 + nt * 8 + (lane >> 2);
                    uint32_t b[2];
                    b[0] = wb[s * 2304 + n * 36 + kw];
                    b[1] = wb[s * 2304 + n * 36 + kw + 4];
#pragma unroll
                    for (int mt = 0; mt < 2; mt++)
                        mma_f16(acc[mt][nt], a[mt], b);
                }
        }

        if (kc < 31) {
            const int nb = cb ^ 1;
            uint32_t* xd = sX + nb * 2304 + lrow * 36 + lk8;
            xd[0] = xr0.x; xd[1] = xr0.y; xd[2] = xr0.z; xd[3] = xr0.w;
            xd[4] = xr1.x; xd[5] = xr1.y; xd[6] = xr1.z; xd[7] = xr1.w;
            uint32_t* w0d = sW2 + nb * 2 * 2304 + lrow * 36 + lk8;
            w0d[0] = wa0.x; w0d[1] = wa0.y; w0d[2] = wa0.z; w0d[3] = wa0.w;
            w0d[4] = wa1.x; w0d[5] = wa1.y; w0d[6] = wa1.z; w0d[7] = wa1.w;
            uint32_t* w1d = w0d + 2304;
            w1d[0] = wb0.x; w1d[1] = wb0.y; w1d[2] = wb0.z; w1d[3] = wb0.w;
            w1d[4] = wb1.x; w1d[5] = wb1.y; w1d[6] = wb1.z; w1d[7] = wb1.w;
        }
    }

    float* outp = g_part + blockIdx.z * (1024 * 256);
    const int r0 = rowbase + wm * 32 + (lane >> 2);
    const int c0 = n0 + wn * 16 + (lane & 3) * 2;
#pragma unroll
    for (int mt = 0; mt < 2; mt++)
#pragma unroll
        for (int nt = 0; nt < 2; nt++) {
            int r = r0 + mt * 16, c = c0 + nt * 8;
            outp[r * 256 + c]           = acc[mt][nt][0];
            outp[r * 256 + c + 1]       = acc[mt][nt][1];
            outp[(r + 8) * 256 + c]     = acc[mt][nt][2];
            outp[(r + 8) * 256 + c + 1] = acc[mt][nt][3];
        }
}

// ---------------------------------------------------------------------------
// Kernel 4: 25-step LIF recurrence — R13 version (reg-resident fc2 frags)
// ---------------------------------------------------------------------------
#define REC_SMEM_BYTES ((32768 + 1280 + 128 + 16 + 256 + 1056 + 1024 + 160) * 4)

__global__ void __launch_bounds__(512, 1) rec_kernel(const float* __restrict__ w2,
                                                     const float* __restrict__ b2,
                                                     const float* __restrict__ w3,
                                                     const float* __restrict__ b3,
                                                     const float* __restrict__ b1,
                                                     float* __restrict__ out) {
    extern __shared__ uint32_t smu[];
    uint32_t* w4f   = smu;
    float* w3s      = (float*)(smu + 32768);
    float* b2s      = w3s + 1280;
    float* b3s      = b2s + 128;
    float* b1s      = b3s + 16;
    __half* spk3h   = (__half*)(b1s + 256);
    float* spk4s    = (float*)((uint32_t*)(b1s + 256) + 1056);
    float* part5    = spk4s + 1024;

    const int t = threadIdx.x;
    const int lane = t & 31, wid = t >> 5;
    const int rowbase = blockIdx.x * 8;

    for (int idx = t; idx < 32768; idx += 512) {
        int reg = idx & 1, ln = (idx >> 1) & 31, s = (idx >> 6) & 1;
        int ks = (idx >> 7) & 15, w = idx >> 11;
        int n = w * 8 + (ln >> 2);
        int kb = ks * 16 + (ln & 3) * 2 + reg * 8;
        float w0 = w2[n * 256 + kb], w1v = w2[n * 256 + kb + 1];
        __half h0, h1;
        if (s == 0) { h0 = __float2half(w0); h1 = __float2half(w1v); }
        else {
            h0 = __float2half(w0 - __half2float(__float2half(w0)));
            h1 = __float2half(w1v - __half2float(__float2half(w1v)));
        }
        w4f[idx] = packh(h0, h1);
    }
    for (int idx = t; idx < 1280; idx += 512) {
        int j = idx >> 7, k = idx & 127;
        w3s[k * 10 + j] = w3[idx];
    }
    if (t < 128) b2s[t] = b2[t];
    if (t < 10)  b3s[t] = b3[t];
    if (t < 256) b1s[t] = b1[t];
    __syncthreads();

    uint2 wreg[16][2];
    {
        const uint32_t* wb = w4f + wid * 2048;
#pragma unroll
        for (int ks = 0; ks < 16; ks++) {
            wreg[ks][0] = *(const uint2*)(wb + ks * 128 + lane * 2);
            wreg[ks][1] = *(const uint2*)(wb + ks * 128 + 64 + lane * 2);
        }
    }

    const int n3 = t & 255, rh = t >> 8;
    float mem3[4], c3[4];
    const int QS = 1024 * 256;
#pragma unroll
    for (int r = 0; r < 4; r++) {
        int row = rowbase + rh * 4 + r;
        mem3[r] = 0.f;
        int off = row * 256 + n3;
        c3[r] = ((g_part[off] + g_part[off + QS]) +
                 (g_part[off + 2 * QS] + g_part[off + 3 * QS])) + b1s[n3];
    }

    const int g4 = lane >> 2, q4 = lane & 3;
    float mem40 = 0.f, mem41 = 0.f;
    const float b2v0 = b2s[wid * 8 + q4 * 2];
    const float b2v1 = b2s[wid * 8 + q4 * 2 + 1];
    float mem5 = 0.f;
    const int rj5 = t % 80, kh5 = (t < 80) ? 0 : 1;
    const int r5 = rj5 / 10, j5 = rj5 % 10;
    const float b3v = (t < 80) ? b3s[j5] : 0.f;

    for (int step = 0; step < NSTEPS; step++) {
#pragma unroll
        for (int r = 0; r < 4; r++) {
            float reset = (mem3[r] > 1.f) ? 1.f : 0.f;
            float m = 0.95f * mem3[r] + c3[r] - reset;
            mem3[r] = m;
            spk3h[(rh * 4 + r) * 264 + n3] = __float2half((m > 1.f) ? 1.f : 0.f);
        }
        __syncthreads();

        {
            float c0[4] = {0.f, 0.f, 0.f, 0.f};
            float c1[4] = {0.f, 0.f, 0.f, 0.f};
            uint32_t a[4];
            a[1] = 0u; a[3] = 0u;
            const __half* ab = spk3h + g4 * 264 + q4 * 2;
#pragma unroll
            for (int ks = 0; ks < 16; ks++) {
                a[0] = *(const uint32_t*)(ab + ks * 16);
                a[2] = *(const uint32_t*)(ab + ks * 16 + 8);
                mma_f16(c0, a, (const uint32_t*)&wreg[ks][0]);
                mma_f16(c1, a, (const uint32_t*)&wreg[ks][1]);
            }
            float cur0 = (c0[0] + c1[0]) + b2v0;
            float cur1 = (c0[1] + c1[1]) + b2v1;
            float reset0 = (mem40 > 1.f) ? 1.f : 0.f;
            float m0 = 0.95f * mem40 + cur0 - reset0;
            mem40 = m0;
            float reset1 = (mem41 > 1.f) ? 1.f : 0.f;
            float m1 = 0.95f * mem41 + cur1 - reset1;
            mem41 = m1;
            int j0 = wid * 8 + q4 * 2;
            spk4s[j0 * 8 + g4]       = (m0 > 1.f) ? 1.f : 0.f;
            spk4s[(j0 + 1) * 8 + g4] = (m1 > 1.f) ? 1.f : 0.f;
        }
        __syncthreads();

        if (t < 160) {
            float a5 = 0.f;
            const int k0 = kh5 * 64;
#pragma unroll 8
            for (int k = k0; k < k0 + 64; k++)
                a5 += w3s[k * 10 + j5] * spk4s[k * 8 + r5];
            part5[kh5 * 80 + rj5] = a5;
        }
        __syncthreads();

        if (t < 80) {
            float a5 = b3v + (part5[t] + part5[80 + t]);
            float reset = (mem5 > 1.f) ? 1.f : 0.f;
            float m = 0.95f * mem5 + a5 - reset;
            mem5 = m;
            out[(step * 1024 + rowbase + r5) * 10 + j5] = (m > 1.f) ? 1.f : 0.f;
        }
    }
}

// ---------------------------------------------------------------------------
extern "C" void kernel_launch(void* const* d_in, const int* in_sizes, int n_in,
                              void* d_out, int out_size) {
    const float* x       = (const float*)d_in[0];
    const float* conv1_w = (const float*)d_in[1];
    const float* conv1_b = (const float*)d_in[2];
    const float* conv2_w = (const float*)d_in[3];
    const float* conv2_b = (const float*)d_in[4];
    const float* fc1_w   = (const float*)d_in[5];
    const float* fc1_b   = (const float*)d_in[6];
    const float* fc2_w   = (const float*)d_in[7];
    const float* fc2_b   = (const float*)d_in[8];
    const float* fc3_w   = (const float*)d_in[9];
    const float* fc3_b   = (const float*)d_in[10];
    float* out = (float*)d_out;

    cudaFuncSetAttribute(conv12_mma, cudaFuncAttributeMaxDynamicSharedMemorySize,
                         C2_SMEM);
    cudaFuncSetAttribute(fc1_mma, cudaFuncAttributeMaxDynamicSharedMemorySize,
                         FC1_SMEM);
    cudaFuncSetAttribute(rec_kernel, cudaFuncAttributeMaxDynamicSharedMemorySize,
                         REC_SMEM_BYTES);

    wprep_kernel<<<8192, 256>>>(fc1_w);
    conv12_mma<<<148, 512, C2_SMEM>>>(x, conv1_w, conv1_b, conv2_w, conv2_b);
    fc1_mma<<<dim3(16, 4, 4), 256, FC1_SMEM>>>();
    rec_kernel<<<128, 512, REC_SMEM_BYTES>>>(fc2_w, fc2_b, fc3_w, fc3_b, fc1_b, out);
}